// round 4
// baseline (speedup 1.0000x reference)
#include <cuda_runtime.h>
#include <math.h>

// Problem constants
#define MM 65536
#define CC 256
#define NCLS 20
#define PP 2048
#define QQ 2048
#define BM 64
#define BN 64
#define BKK 32

__device__ __constant__ float c_margin = 0.3f;
#define EPSV (0.0001f / 256.0f)

// Scratch (static device globals; no runtime allocation)
__device__ float g_pos[(size_t)NCLS * PP * CC];     // gathered sigmoid(pos rows)
__device__ float g_neg[(size_t)NCLS * QQ * CC];     // gathered sigmoid(neg rows)
__device__ float g_pos_sq[NCLS * PP];               // row squared norms
__device__ float g_neg_sq[NCLS * QQ];
__device__ int   g_hp[NCLS * PP];                   // hardest positive index per anchor
__device__ int   g_hn[NCLS * PP];                   // hardest negative index per anchor
__device__ float g_partial[NCLS * PP / 8];          // per-block loss partials (5120)

// ---------------------------------------------------------------------------
// Kernel 1: gather rows, apply sigmoid, store row + squared norm.
// One block (64 threads) per gathered row; each thread handles one float4.
// ---------------------------------------------------------------------------
__global__ void __launch_bounds__(64) gather_kernel(const float* __restrict__ feat,
                                                    const int* __restrict__ pidx,
                                                    const int* __restrict__ nidx) {
    int row = blockIdx.x;          // 0 .. NCLS*(PP+QQ)-1
    int t = threadIdx.x;           // 0 .. 63
    int src;
    float* dst;
    float* sqdst;
    if (row < NCLS * PP) {
        src = pidx[row];
        dst = g_pos + (size_t)row * CC;
        sqdst = g_pos_sq + row;
    } else {
        int r = row - NCLS * PP;
        src = nidx[r];
        dst = g_neg + (size_t)r * CC;
        sqdst = g_neg_sq + r;
    }
    float4 v = *(const float4*)(feat + (size_t)src * CC + t * 4);
    float4 s;
    s.x = 1.0f / (1.0f + expf(-v.x));
    s.y = 1.0f / (1.0f + expf(-v.y));
    s.z = 1.0f / (1.0f + expf(-v.z));
    s.w = 1.0f / (1.0f + expf(-v.w));
    *(float4*)(dst + t * 4) = s;

    float ss = s.x * s.x + s.y * s.y + s.z * s.z + s.w * s.w;
    #pragma unroll
    for (int o = 16; o > 0; o >>= 1) ss += __shfl_xor_sync(0xffffffffu, ss, o);
    __shared__ float part[2];
    if ((t & 31) == 0) part[t >> 5] = ss;
    __syncthreads();
    if (t == 0) *sqdst = part[0] + part[1];
}

// ---------------------------------------------------------------------------
// Kernel 2: fused mining GEMM.
// Block = (row-tile of 64 anchors, class). 128 threads.
// For each 64-col tile of pos (argmax) then neg (argmin), accumulate the
// 64x64 dot-product tile via SMEM-tiled fp32 FMA (K-tile = 32), form
// dis = clip(xx_i - 2*xy + yy_j, 0), keep running best (first-index ties).
// ---------------------------------------------------------------------------
__global__ void __launch_bounds__(128) mine_kernel() {
    const int cls  = blockIdx.y;
    const int row0 = blockIdx.x * BM;
    const int t  = threadIdx.x;
    const int ty = t >> 3;          // 0..15  (row group, TM=4 stride 16)
    const int tx = t & 7;           // 0..7   (col group, TN=8 stride 8)
    const int lr = t >> 3;          // 0..15  load row base
    const int lc = (t & 7) << 2;    // 0,4,...,28 load col (float4)

    __shared__ float As[BM][BKK + 1];
    __shared__ float Bs[BN][BKK + 1];
    __shared__ float sV[BM][8];
    __shared__ int   sI[BM][8];

    const float* Abase = g_pos + ((size_t)cls * PP + row0) * CC;

    float xx[4];
    #pragma unroll
    for (int m = 0; m < 4; m++) xx[m] = g_pos_sq[cls * PP + row0 + ty + 16 * m];

    float bmaxv[4], bminv[4];
    int   bmaxj[4], bminj[4];
    #pragma unroll
    for (int m = 0; m < 4; m++) {
        bmaxv[m] = -1e30f; bmaxj[m] = 0;
        bminv[m] =  1e30f; bminj[m] = 0;
    }

    for (int pass = 0; pass < 2; pass++) {
        const float* Bbase = pass ? (g_neg + (size_t)cls * QQ * CC)
                                  : (g_pos + (size_t)cls * PP * CC);
        const float* yyb   = pass ? (g_neg_sq + cls * QQ)
                                  : (g_pos_sq + cls * PP);
        const int NJ = (pass ? QQ : PP) / BN;
        for (int jt = 0; jt < NJ; jt++) {
            float acc[4][8];
            #pragma unroll
            for (int m = 0; m < 4; m++)
                #pragma unroll
                for (int n = 0; n < 8; n++) acc[m][n] = 0.0f;

            const float* Bt = Bbase + (size_t)jt * BN * CC;
            for (int kk = 0; kk < CC; kk += BKK) {
                // 64x32 tile each of A and B: 4 rows per thread (lr, +16, +32, +48)
                #pragma unroll
                for (int rr = 0; rr < 4; rr++) {
                    int r = lr + 16 * rr;
                    float4 av = *(const float4*)(Abase + (size_t)r * CC + kk + lc);
                    float4 bv = *(const float4*)(Bt + (size_t)r * CC + kk + lc);
                    As[r][lc + 0] = av.x; As[r][lc + 1] = av.y;
                    As[r][lc + 2] = av.z; As[r][lc + 3] = av.w;
                    Bs[r][lc + 0] = bv.x; Bs[r][lc + 1] = bv.y;
                    Bs[r][lc + 2] = bv.z; Bs[r][lc + 3] = bv.w;
                }
                __syncthreads();
                #pragma unroll
                for (int kc = 0; kc < BKK; kc++) {
                    float a[4], b[8];
                    #pragma unroll
                    for (int m = 0; m < 4; m++) a[m] = As[ty + 16 * m][kc];
                    #pragma unroll
                    for (int n = 0; n < 8; n++) b[n] = Bs[tx + 8 * n][kc];
                    #pragma unroll
                    for (int m = 0; m < 4; m++)
                        #pragma unroll
                        for (int n = 0; n < 8; n++)
                            acc[m][n] = fmaf(a[m], b[n], acc[m][n]);
                }
                __syncthreads();
            }
            // Epilogue: distances + running best. Within a thread, j is
            // strictly ascending, so strict compare keeps the first index.
            #pragma unroll
            for (int n = 0; n < 8; n++) {
                int j = jt * BN + tx + 8 * n;
                float yy = yyb[j];
                #pragma unroll
                for (int m = 0; m < 4; m++) {
                    float dis = fmaxf(fmaf(-2.0f, acc[m][n], xx[m] + yy), 0.0f);
                    if (pass == 0) {
                        if (dis > bmaxv[m]) { bmaxv[m] = dis; bmaxj[m] = j; }
                    } else {
                        if (dis < bminv[m]) { bminv[m] = dis; bminj[m] = j; }
                    }
                }
            }
        }
    }

    // Cross-thread reduction (8 column-groups per row); tie-break on index.
    #pragma unroll
    for (int m = 0; m < 4; m++) {
        sV[ty + 16 * m][tx] = bmaxv[m];
        sI[ty + 16 * m][tx] = bmaxj[m];
    }
    __syncthreads();
    if (t < BM) {
        float bv = sV[t][0]; int bj = sI[t][0];
        #pragma unroll
        for (int x = 1; x < 8; x++) {
            float v = sV[t][x]; int j = sI[t][x];
            if (v > bv || (v == bv && j < bj)) { bv = v; bj = j; }
        }
        g_hp[cls * PP + row0 + t] = bj;
    }
    __syncthreads();
    #pragma unroll
    for (int m = 0; m < 4; m++) {
        sV[ty + 16 * m][tx] = bminv[m];
        sI[ty + 16 * m][tx] = bminj[m];
    }
    __syncthreads();
    if (t < BM) {
        float bv = sV[t][0]; int bj = sI[t][0];
        #pragma unroll
        for (int x = 1; x < 8; x++) {
            float v = sV[t][x]; int j = sI[t][x];
            if (v < bv || (v == bv && j < bj)) { bv = v; bj = j; }
        }
        g_hn[cls * PP + row0 + t] = bj;
    }
}

// ---------------------------------------------------------------------------
// Kernel 3: per-anchor pdist + hinge. One warp per anchor, 8 warps/block.
// Deterministic: per-block partial sums, no atomics.
// ---------------------------------------------------------------------------
__global__ void __launch_bounds__(256) loss_kernel() {
    int warp = threadIdx.x >> 5;
    int lane = threadIdx.x & 31;
    int a = blockIdx.x * 8 + warp;       // anchor id, 0 .. NCLS*PP-1
    int cls = a / PP;

    const float* x  = g_pos + (size_t)a * CC;
    const float* yp = g_pos + ((size_t)cls * PP + g_hp[a]) * CC;
    const float* yn = g_neg + ((size_t)cls * QQ + g_hn[a]) * CC;

    float sp = 0.0f, sn = 0.0f;
    #pragma unroll
    for (int c4 = lane; c4 < CC / 4; c4 += 32) {
        float4 xv = ((const float4*)x)[c4];
        float4 pv = ((const float4*)yp)[c4];
        float4 nv = ((const float4*)yn)[c4];
        float d;
        d = xv.x - pv.x; sp = fmaf(d, d, sp);
        d = xv.y - pv.y; sp = fmaf(d, d, sp);
        d = xv.z - pv.z; sp = fmaf(d, d, sp);
        d = xv.w - pv.w; sp = fmaf(d, d, sp);
        d = xv.x - nv.x; sn = fmaf(d, d, sn);
        d = xv.y - nv.y; sn = fmaf(d, d, sn);
        d = xv.z - nv.z; sn = fmaf(d, d, sn);
        d = xv.w - nv.w; sn = fmaf(d, d, sn);
    }
    #pragma unroll
    for (int o = 16; o > 0; o >>= 1) {
        sp += __shfl_xor_sync(0xffffffffu, sp, o);
        sn += __shfl_xor_sync(0xffffffffu, sn, o);
    }
    __shared__ float sl[8];
    if (lane == 0) {
        float dp = sqrtf(fmaxf(sp, 0.0f) + EPSV);
        float dn = sqrtf(fmaxf(sn, 0.0f) + EPSV);
        sl[warp] = fmaxf(c_margin + dp - dn, 0.0f);
    }
    __syncthreads();
    if (threadIdx.x == 0) {
        float s = 0.0f;
        #pragma unroll
        for (int w = 0; w < 8; w++) s += sl[w];
        g_partial[blockIdx.x] = s * (1.0f / (float)PP);
    }
}

// ---------------------------------------------------------------------------
// Kernel 4: deterministic final reduction of 5120 partials.
// ---------------------------------------------------------------------------
__global__ void __launch_bounds__(1024) finalsum_kernel(float* __restrict__ out) {
    __shared__ float s[1024];
    float v = 0.0f;
    for (int i = threadIdx.x; i < NCLS * PP / 8; i += 1024) v += g_partial[i];
    s[threadIdx.x] = v;
    __syncthreads();
    for (int st = 512; st > 0; st >>= 1) {
        if (threadIdx.x < st) s[threadIdx.x] += s[threadIdx.x + st];
        __syncthreads();
    }
    if (threadIdx.x == 0) out[0] = s[0];
}

extern "C" void kernel_launch(void* const* d_in, const int* in_sizes, int n_in,
                              void* d_out, int out_size) {
    const float* feat = (const float*)d_in[0];
    const int* pidx = (const int*)d_in[1];
    const int* nidx = (const int*)d_in[2];
    float* out = (float*)d_out;

    gather_kernel<<<NCLS * (PP + QQ), 64>>>(feat, pidx, nidx);
    mine_kernel<<<dim3(PP / BM, NCLS), 128>>>();
    loss_kernel<<<NCLS * PP / 8, 256>>>();
    finalsum_kernel<<<1, 1024>>>(out);
}

// round 9
// speedup vs baseline: 2.0054x; 2.0054x over previous
#include <cuda_runtime.h>
#include <cuda_bf16.h>
#include <math.h>
#include <stdint.h>

// ---------------- problem constants ----------------
#define NCLS 20
#define PP 2048
#define QQ 2048
#define CC 256
#define EPSV (0.0001f / 256.0f)

// ext row: [hi(256) | lo(256)] bf16 = 1024 bytes
#define ROW_BYTES 1024

// ---------------- device scratch (static; no runtime alloc) ----------------
__device__ float g_pos[(size_t)NCLS * PP * CC];
__device__ float g_neg[(size_t)NCLS * QQ * CC];
__device__ float g_pos_sq[NCLS * PP];
__device__ float g_neg_sq[NCLS * QQ];
__device__ __align__(16) unsigned char g_posb[(size_t)NCLS * PP * ROW_BYTES];
__device__ __align__(16) unsigned char g_negb[(size_t)NCLS * QQ * ROW_BYTES];
__device__ int   g_hp[NCLS * PP];
__device__ int   g_hn[NCLS * PP];
__device__ float g_partial[NCLS * PP / 8];

// ---------------- helpers ----------------
__device__ __forceinline__ uint32_t smem_u32(const void* p) {
    uint32_t a;
    asm("{ .reg .u64 t; cvta.to.shared.u64 t, %1; cvt.u32.u64 %0, t; }" : "=r"(a) : "l"(p));
    return a;
}
#define CP_ASYNC16(saddr, gptr) \
    asm volatile("cp.async.cg.shared.global [%0], [%1], 16;" :: "r"(saddr), "l"(gptr))
#define CP_COMMIT() asm volatile("cp.async.commit_group;" ::: "memory")
#define CP_WAIT1()  asm volatile("cp.async.wait_group 1;" ::: "memory")
#define CP_WAIT0()  asm volatile("cp.async.wait_group 0;" ::: "memory")

#define LDSM_X4(r0, r1, r2, r3, a) \
    asm volatile("ldmatrix.sync.aligned.m8n8.x4.shared.b16 {%0,%1,%2,%3}, [%4];" \
                 : "=r"(r0), "=r"(r1), "=r"(r2), "=r"(r3) : "r"(a))
#define LDSM_X2(r0, r1, a) \
    asm volatile("ldmatrix.sync.aligned.m8n8.x2.shared.b16 {%0,%1}, [%2];" \
                 : "=r"(r0), "=r"(r1) : "r"(a))
#define MMA16816(c0, c1, c2, c3, a0, a1, a2, a3, b0, b1) \
    asm volatile("mma.sync.aligned.m16n8k16.row.col.f32.bf16.bf16.f32 " \
                 "{%0,%1,%2,%3}, {%4,%5,%6,%7}, {%8,%9}, {%0,%1,%2,%3};" \
                 : "+f"(c0), "+f"(c1), "+f"(c2), "+f"(c3) \
                 : "r"(a0), "r"(a1), "r"(a2), "r"(a3), "r"(b0), "r"(b1))

__device__ __forceinline__ uint32_t pack_bf16(float a, float b) {
    __nv_bfloat16 ba = __float2bfloat16(a);
    __nv_bfloat16 bb = __float2bfloat16(b);
    uint16_t ua = *reinterpret_cast<uint16_t*>(&ba);
    uint16_t ub = *reinterpret_cast<uint16_t*>(&bb);
    return ((uint32_t)ub << 16) | (uint32_t)ua;
}

// ---------------------------------------------------------------------------
// Kernel 1: gather + sigmoid -> fp32 row, squared norm, and hi|lo bf16 ext row
// (plain row-major: hi at bytes [0,512), lo at [512,1024)).
// ---------------------------------------------------------------------------
__global__ void __launch_bounds__(64) gather_kernel(const float* __restrict__ feat,
                                                    const int* __restrict__ pidx,
                                                    const int* __restrict__ nidx) {
    int row = blockIdx.x;
    int t = threadIdx.x;
    int src;
    float* dst;
    float* sqdst;
    unsigned char* rb;
    if (row < NCLS * PP) {
        src = pidx[row];
        dst = g_pos + (size_t)row * CC;
        sqdst = g_pos_sq + row;
        rb = g_posb + (size_t)row * ROW_BYTES;
    } else {
        int r = row - NCLS * PP;
        src = nidx[r];
        dst = g_neg + (size_t)r * CC;
        sqdst = g_neg_sq + r;
        rb = g_negb + (size_t)r * ROW_BYTES;
    }
    float4 v = *(const float4*)(feat + (size_t)src * CC + t * 4);
    float4 s;
    s.x = 1.0f / (1.0f + expf(-v.x));
    s.y = 1.0f / (1.0f + expf(-v.y));
    s.z = 1.0f / (1.0f + expf(-v.z));
    s.w = 1.0f / (1.0f + expf(-v.w));
    *(float4*)(dst + t * 4) = s;

    __nv_bfloat16 h0 = __float2bfloat16(s.x);
    __nv_bfloat16 h1 = __float2bfloat16(s.y);
    __nv_bfloat16 h2 = __float2bfloat16(s.z);
    __nv_bfloat16 h3 = __float2bfloat16(s.w);
    uint16_t u0 = *reinterpret_cast<uint16_t*>(&h0);
    uint16_t u1 = *reinterpret_cast<uint16_t*>(&h1);
    uint16_t u2 = *reinterpret_cast<uint16_t*>(&h2);
    uint16_t u3 = *reinterpret_cast<uint16_t*>(&h3);
    uint2 hv, lv;
    hv.x = ((uint32_t)u1 << 16) | u0;
    hv.y = ((uint32_t)u3 << 16) | u2;
    lv.x = pack_bf16(s.x - __bfloat162float(h0), s.y - __bfloat162float(h1));
    lv.y = pack_bf16(s.z - __bfloat162float(h2), s.w - __bfloat162float(h3));
    *(uint2*)(rb + t * 8) = hv;
    *(uint2*)(rb + 512 + t * 8) = lv;

    float ss = s.x * s.x + s.y * s.y + s.z * s.z + s.w * s.w;
    #pragma unroll
    for (int o = 16; o > 0; o >>= 1) ss += __shfl_xor_sync(0xffffffffu, ss, o);
    __shared__ float part[2];
    if ((t & 31) == 0) part[t >> 5] = ss;
    __syncthreads();
    if (t == 0) *sqdst = part[0] + part[1];
}

// ---------------------------------------------------------------------------
// Kernel 2: mma.sync mining GEMM.
// CTA = 128 anchors x class. 256 threads (8 warps in 2x4). A ext tile resident
// in SMEM (128KB). B streamed in 32KB chunks (128 cand x 128 elems), cp.async
// double-buffered. 3-segment hi/lo schedule (K=768 effective) for accuracy.
// Epilogue: dis = clip(xx + yy - 2 acc, 0); running argmax (pos) / argmin (neg).
// ---------------------------------------------------------------------------
#define OFF_A   0u
#define OFF_B0  131072u
#define OFF_B1  163840u
#define OFF_YY0 196608u
#define OFF_YY1 197120u
#define SMEM_SZ 197632

__constant__ int c_aoffd8[6] = {0, 16, 32, 48, 0, 16};     // A seg offset in 16B units
__constant__ int c_boff[6]   = {0, 256, 0, 256, 512, 768}; // B seg offset bytes

__device__ __forceinline__ void prefetch_chunk(int g, uint32_t bufoff, int tid,
                                               uint32_t sbase,
                                               const unsigned char* posb,
                                               const unsigned char* negb,
                                               const float* psq, const float* nsq) {
    int jt = g / 6, c = g - jt * 6;
    const unsigned char* rb = (jt < 16)
        ? (posb + (size_t)(jt * 128) * ROW_BYTES)
        : (negb + (size_t)((jt - 16) * 128) * ROW_BYTES);
    rb += c_boff[c];
    uint32_t dst = sbase + bufoff;
    #pragma unroll
    for (int it = 0; it < 8; it++) {
        int i = tid + it * 256;
        int r = i >> 4, cl = i & 15;
        uint32_t cls16 = (uint32_t)((cl & 8) | ((cl ^ r) & 7));
        CP_ASYNC16(dst + (uint32_t)r * 256u + cls16 * 16u,
                   rb + (size_t)r * ROW_BYTES + cl * 16);
    }
    if (c == 0 && tid < 32) {
        const float* ys = (jt < 16) ? (psq + jt * 128) : (nsq + (jt - 16) * 128);
        CP_ASYNC16(sbase + ((jt & 1) ? OFF_YY1 : OFF_YY0) + (uint32_t)tid * 16u,
                   ys + tid * 4);
    }
}

__global__ void __launch_bounds__(256, 1) mine_kernel() {
    extern __shared__ __align__(16) unsigned char smem[];
    const int cls  = blockIdx.y;
    const int row0 = blockIdx.x * 128;
    const int tid  = threadIdx.x;
    const int lane = tid & 31;
    const int wid  = tid >> 5;
    const int wm   = wid >> 2;        // 0..1
    const int wn   = wid & 3;         // 0..3
    const uint32_t sbase = smem_u32(smem);

    const unsigned char* posb = g_posb + (size_t)cls * PP * ROW_BYTES;
    const unsigned char* negb = g_negb + (size_t)cls * QQ * ROW_BYTES;
    const float* psq = g_pos_sq + cls * PP;
    const float* nsq = g_neg_sq + cls * QQ;

    // ---- load resident A ext tile (128 rows x 1KB), swizzled ----
    {
        const unsigned char* asrc = posb + (size_t)row0 * ROW_BYTES;
        #pragma unroll
        for (int it = 0; it < 32; it++) {
            int i = tid + it * 256;          // 0..8191
            int r = i >> 6, c16 = i & 63;
            uint32_t c16s = (uint32_t)((c16 & ~7) | ((c16 ^ r) & 7));
            CP_ASYNC16(sbase + OFF_A + (uint32_t)r * 1024u + c16s * 16u,
                       asrc + (size_t)r * ROW_BYTES + c16 * 16);
        }
    }
    CP_COMMIT();
    CP_WAIT0();
    __syncthreads();

    // ---- per-lane constants ----
    const int rrA = wm * 64 + (lane & 15);       // A ldmatrix row (within 128)
    const int khA = (lane >> 4) & 1;
    const int nB  = wn * 32 + (lane & 7);        // B ldmatrix row base
    const int khB = (lane >> 3) & 1;
    uint32_t aRow[4];
    #pragma unroll
    for (int mt = 0; mt < 4; mt++) aRow[mt] = sbase + OFF_A + (uint32_t)(rrA + mt * 16) * 1024u;

    // xx for owned rows
    float xxv[8];
    #pragma unroll
    for (int mt = 0; mt < 4; mt++) {
        int r0 = wm * 64 + mt * 16 + (lane >> 2);
        xxv[mt * 2]     = psq[row0 + r0];
        xxv[mt * 2 + 1] = psq[row0 + r0 + 8];
    }

    float acc[64];
    #pragma unroll
    for (int i = 0; i < 64; i++) acc[i] = 0.0f;

    float bpv[8], bnv[8];
    int   bpj[8], bnj[8];
    #pragma unroll
    for (int i = 0; i < 8; i++) {
        bpv[i] = -1e30f; bpj[i] = 0;
        bnv[i] =  1e30f; bnj[i] = 0;
    }

    prefetch_chunk(0, OFF_B0, tid, sbase, posb, negb, psq, nsq);
    CP_COMMIT();

    for (int g = 0; g < 192; g++) {
        __syncthreads();                       // prior compute done; safe to overwrite
        if (g + 1 < 192) {
            prefetch_chunk(g + 1, ((g + 1) & 1) ? OFF_B1 : OFF_B0, tid, sbase,
                           posb, negb, psq, nsq);
            CP_COMMIT();
            CP_WAIT1();
        } else {
            CP_WAIT0();
        }
        __syncthreads();                       // buffer g visible to all warps

        const uint32_t sbB = sbase + ((g & 1) ? OFF_B1 : OFF_B0);
        const int jt = g / 6, c = g - jt * 6;
        const int aoffd8 = c_aoffd8[c];
        uint32_t bRow[4];
        #pragma unroll
        for (int nt = 0; nt < 4; nt++) bRow[nt] = sbB + (uint32_t)(nB + nt * 8) * 256u;

        #pragma unroll
        for (int k16 = 0; k16 < 8; k16++) {
            uint32_t a0[4], a1[4], a2[4], a3[4];
            #pragma unroll
            for (int mt = 0; mt < 4; mt++) {
                int c16 = aoffd8 + k16 * 2 + khA;
                uint32_t c16s = (uint32_t)((c16 & ~7) | ((c16 ^ rrA) & 7));
                LDSM_X4(a0[mt], a1[mt], a2[mt], a3[mt], aRow[mt] + c16s * 16u);
            }
            uint32_t b0[4], b1[4];
            #pragma unroll
            for (int nt = 0; nt < 4; nt++) {
                int cl = k16 * 2 + khB;
                uint32_t cls16 = (uint32_t)((cl & 8) | ((cl ^ nB) & 7));
                LDSM_X2(b0[nt], b1[nt], bRow[nt] + cls16 * 16u);
            }
            #pragma unroll
            for (int mt = 0; mt < 4; mt++)
                #pragma unroll
                for (int nt = 0; nt < 4; nt++) {
                    int ai = (mt * 4 + nt) * 4;
                    MMA16816(acc[ai], acc[ai + 1], acc[ai + 2], acc[ai + 3],
                             a0[mt], a1[mt], a2[mt], a3[mt], b0[nt], b1[nt]);
                }
        }

        if (c == 5) {
            // epilogue for j-tile jt
            const float* yy = (const float*)(smem + ((jt & 1) ? OFF_YY1 : OFF_YY0));
            const bool isneg = jt >= 16;
            const int jbase = (isneg ? (jt - 16) : jt) * 128 + wn * 32;
            #pragma unroll
            for (int mt = 0; mt < 4; mt++) {
                #pragma unroll
                for (int nt = 0; nt < 4; nt++) {
                    int ai = (mt * 4 + nt) * 4;
                    int n = nt * 8 + ((lane & 3) << 1);
                    float y0 = yy[wn * 32 + n], y1 = yy[wn * 32 + n + 1];
                    float d00 = fmaxf(xxv[mt*2]   + y0 - 2.0f * acc[ai],     0.0f);
                    float d01 = fmaxf(xxv[mt*2]   + y1 - 2.0f * acc[ai + 1], 0.0f);
                    float d10 = fmaxf(xxv[mt*2+1] + y0 - 2.0f * acc[ai + 2], 0.0f);
                    float d11 = fmaxf(xxv[mt*2+1] + y1 - 2.0f * acc[ai + 3], 0.0f);
                    int j0 = jbase + n, j1 = j0 + 1;
                    if (!isneg) {
                        if (d00 > bpv[mt*2])   { bpv[mt*2]   = d00; bpj[mt*2]   = j0; }
                        if (d01 > bpv[mt*2])   { bpv[mt*2]   = d01; bpj[mt*2]   = j1; }
                        if (d10 > bpv[mt*2+1]) { bpv[mt*2+1] = d10; bpj[mt*2+1] = j0; }
                        if (d11 > bpv[mt*2+1]) { bpv[mt*2+1] = d11; bpj[mt*2+1] = j1; }
                    } else {
                        if (d00 < bnv[mt*2])   { bnv[mt*2]   = d00; bnj[mt*2]   = j0; }
                        if (d01 < bnv[mt*2])   { bnv[mt*2]   = d01; bnj[mt*2]   = j1; }
                        if (d10 < bnv[mt*2+1]) { bnv[mt*2+1] = d10; bnj[mt*2+1] = j0; }
                        if (d11 < bnv[mt*2+1]) { bnv[mt*2+1] = d11; bnj[mt*2+1] = j1; }
                    }
                    acc[ai] = acc[ai + 1] = acc[ai + 2] = acc[ai + 3] = 0.0f;
                }
            }
        }
    }

    // ---- final cross-copy reduction (16 copies per row) ----
    __syncthreads();
    float* sPV = (float*)(smem + OFF_B0);
    int*   sPJ = (int*)(smem + OFF_B0 + 8192);
    float* sNV = (float*)(smem + OFF_B0 + 16384);
    int*   sNJ = (int*)(smem + OFF_B0 + 24576);
    int copy = wn * 4 + (lane & 3);
    #pragma unroll
    for (int mt = 0; mt < 4; mt++) {
        #pragma unroll
        for (int h = 0; h < 2; h++) {
            int r = wm * 64 + mt * 16 + (lane >> 2) + 8 * h;
            sPV[r * 16 + copy] = bpv[mt * 2 + h];
            sPJ[r * 16 + copy] = bpj[mt * 2 + h];
            sNV[r * 16 + copy] = bnv[mt * 2 + h];
            sNJ[r * 16 + copy] = bnj[mt * 2 + h];
        }
    }
    __syncthreads();
    if (tid < 128) {
        int r = tid;
        float bv = sPV[r * 16]; int bj = sPJ[r * 16];
        #pragma unroll
        for (int x = 1; x < 16; x++) {
            float v = sPV[r * 16 + x]; int j = sPJ[r * 16 + x];
            if (v > bv || (v == bv && j < bj)) { bv = v; bj = j; }
        }
        g_hp[cls * PP + row0 + r] = bj;
        bv = sNV[r * 16]; bj = sNJ[r * 16];
        #pragma unroll
        for (int x = 1; x < 16; x++) {
            float v = sNV[r * 16 + x]; int j = sNJ[r * 16 + x];
            if (v < bv || (v == bv && j < bj)) { bv = v; bj = j; }
        }
        g_hn[cls * PP + row0 + r] = bj;
    }
}

// ---------------------------------------------------------------------------
// Kernel 3: per-anchor pdist + hinge (fp32 exact). One warp per anchor.
// ---------------------------------------------------------------------------
__global__ void __launch_bounds__(256) loss_kernel() {
    int warp = threadIdx.x >> 5;
    int lane = threadIdx.x & 31;
    int a = blockIdx.x * 8 + warp;
    int cls = a / PP;

    const float* x  = g_pos + (size_t)a * CC;
    const float* yp = g_pos + ((size_t)cls * PP + g_hp[a]) * CC;
    const float* yn = g_neg + ((size_t)cls * QQ + g_hn[a]) * CC;

    float sp = 0.0f, sn = 0.0f;
    #pragma unroll
    for (int c4 = lane; c4 < CC / 4; c4 += 32) {
        float4 xv = ((const float4*)x)[c4];
        float4 pv = ((const float4*)yp)[c4];
        float4 nv = ((const float4*)yn)[c4];
        float d;
        d = xv.x - pv.x; sp = fmaf(d, d, sp);
        d = xv.y - pv.y; sp = fmaf(d, d, sp);
        d = xv.z - pv.z; sp = fmaf(d, d, sp);
        d = xv.w - pv.w; sp = fmaf(d, d, sp);
        d = xv.x - nv.x; sn = fmaf(d, d, sn);
        d = xv.y - nv.y; sn = fmaf(d, d, sn);
        d = xv.z - nv.z; sn = fmaf(d, d, sn);
        d = xv.w - nv.w; sn = fmaf(d, d, sn);
    }
    #pragma unroll
    for (int o = 16; o > 0; o >>= 1) {
        sp += __shfl_xor_sync(0xffffffffu, sp, o);
        sn += __shfl_xor_sync(0xffffffffu, sn, o);
    }
    __shared__ float sl[8];
    if (lane == 0) {
        float dp = sqrtf(fmaxf(sp, 0.0f) + EPSV);
        float dn = sqrtf(fmaxf(sn, 0.0f) + EPSV);
        sl[warp] = fmaxf(0.3f + dp - dn, 0.0f);
    }
    __syncthreads();
    if (threadIdx.x == 0) {
        float s = 0.0f;
        #pragma unroll
        for (int w = 0; w < 8; w++) s += sl[w];
        g_partial[blockIdx.x] = s * (1.0f / (float)PP);
    }
}

__global__ void __launch_bounds__(1024) finalsum_kernel(float* __restrict__ out) {
    __shared__ float s[1024];
    float v = 0.0f;
    for (int i = threadIdx.x; i < NCLS * PP / 8; i += 1024) v += g_partial[i];
    s[threadIdx.x] = v;
    __syncthreads();
    for (int st = 512; st > 0; st >>= 1) {
        if (threadIdx.x < st) s[threadIdx.x] += s[threadIdx.x + st];
        __syncthreads();
    }
    if (threadIdx.x == 0) out[0] = s[0];
}

extern "C" void kernel_launch(void* const* d_in, const int* in_sizes, int n_in,
                              void* d_out, int out_size) {
    const float* feat = (const float*)d_in[0];
    const int* pidx = (const int*)d_in[1];
    const int* nidx = (const int*)d_in[2];
    float* out = (float*)d_out;

    cudaFuncSetAttribute(mine_kernel, cudaFuncAttributeMaxDynamicSharedMemorySize, SMEM_SZ);

    gather_kernel<<<NCLS * (PP + QQ), 64>>>(feat, pidx, nidx);
    mine_kernel<<<dim3(PP / 128, NCLS), 256, SMEM_SZ>>>();
    loss_kernel<<<NCLS * PP / 8, 256>>>();
    finalsum_kernel<<<1, 1024>>>(out);
}

// round 12
// speedup vs baseline: 3.3493x; 1.6701x over previous
#include <cuda_runtime.h>
#include <cuda_bf16.h>
#include <math.h>
#include <stdint.h>

// ---------------- problem constants ----------------
#define NCLS 20
#define PP 2048
#define QQ 2048
#define CC 256
#define EPSV (0.0001f / 256.0f)

// ext row: [hi(256) | lo(256)] bf16 = 1024 bytes
#define ROW_BYTES 1024

// ---------------- device scratch (static; no runtime alloc) ----------------
__device__ float g_pos[(size_t)NCLS * PP * CC];
__device__ float g_neg[(size_t)NCLS * QQ * CC];
__device__ float g_pos_sq[NCLS * PP];
__device__ float g_neg_sq[NCLS * QQ];
__device__ __align__(16) unsigned char g_posb[(size_t)NCLS * PP * ROW_BYTES];
__device__ __align__(16) unsigned char g_negb[(size_t)NCLS * QQ * ROW_BYTES];
__device__ int   g_hp[NCLS * PP];
__device__ int   g_hn[NCLS * PP];
__device__ float g_partial[NCLS * PP / 8];

// ---------------- helpers ----------------
__device__ __forceinline__ uint32_t smem_u32(const void* p) {
    uint32_t a;
    asm("{ .reg .u64 t; cvta.to.shared.u64 t, %1; cvt.u32.u64 %0, t; }" : "=r"(a) : "l"(p));
    return a;
}
#define CP_ASYNC16(saddr, gptr) \
    asm volatile("cp.async.cg.shared.global [%0], [%1], 16;" :: "r"(saddr), "l"(gptr))
#define CP_COMMIT() asm volatile("cp.async.commit_group;" ::: "memory")
#define CP_WAIT1()  asm volatile("cp.async.wait_group 1;" ::: "memory")
#define CP_WAIT0()  asm volatile("cp.async.wait_group 0;" ::: "memory")

#define LDSM_X4(r0, r1, r2, r3, a) \
    asm volatile("ldmatrix.sync.aligned.m8n8.x4.shared.b16 {%0,%1,%2,%3}, [%4];" \
                 : "=r"(r0), "=r"(r1), "=r"(r2), "=r"(r3) : "r"(a))
#define LDSM_X2(r0, r1, a) \
    asm volatile("ldmatrix.sync.aligned.m8n8.x2.shared.b16 {%0,%1}, [%2];" \
                 : "=r"(r0), "=r"(r1) : "r"(a))
#define MMA16816(c0, c1, c2, c3, a0, a1, a2, a3, b0, b1) \
    asm volatile("mma.sync.aligned.m16n8k16.row.col.f32.bf16.bf16.f32 " \
                 "{%0,%1,%2,%3}, {%4,%5,%6,%7}, {%8,%9}, {%0,%1,%2,%3};" \
                 : "+f"(c0), "+f"(c1), "+f"(c2), "+f"(c3) \
                 : "r"(a0), "r"(a1), "r"(a2), "r"(a3), "r"(b0), "r"(b1))

__device__ __forceinline__ uint32_t pack_bf16(float a, float b) {
    __nv_bfloat16 ba = __float2bfloat16(a);
    __nv_bfloat16 bb = __float2bfloat16(b);
    uint16_t ua = *reinterpret_cast<uint16_t*>(&ba);
    uint16_t ub = *reinterpret_cast<uint16_t*>(&bb);
    return ((uint32_t)ub << 16) | (uint32_t)ua;
}

// ---------------------------------------------------------------------------
// Kernel 1: gather + sigmoid -> fp32 row, squared norm, and hi|lo bf16 ext row
// (plain row-major: hi at bytes [0,512), lo at [512,1024)).
// ---------------------------------------------------------------------------
__global__ void __launch_bounds__(64) gather_kernel(const float* __restrict__ feat,
                                                    const int* __restrict__ pidx,
                                                    const int* __restrict__ nidx) {
    int row = blockIdx.x;
    int t = threadIdx.x;
    int src;
    float* dst;
    float* sqdst;
    unsigned char* rb;
    if (row < NCLS * PP) {
        src = pidx[row];
        dst = g_pos + (size_t)row * CC;
        sqdst = g_pos_sq + row;
        rb = g_posb + (size_t)row * ROW_BYTES;
    } else {
        int r = row - NCLS * PP;
        src = nidx[r];
        dst = g_neg + (size_t)r * CC;
        sqdst = g_neg_sq + r;
        rb = g_negb + (size_t)r * ROW_BYTES;
    }
    float4 v = *(const float4*)(feat + (size_t)src * CC + t * 4);
    float4 s;
    s.x = 1.0f / (1.0f + expf(-v.x));
    s.y = 1.0f / (1.0f + expf(-v.y));
    s.z = 1.0f / (1.0f + expf(-v.z));
    s.w = 1.0f / (1.0f + expf(-v.w));
    *(float4*)(dst + t * 4) = s;

    __nv_bfloat16 h0 = __float2bfloat16(s.x);
    __nv_bfloat16 h1 = __float2bfloat16(s.y);
    __nv_bfloat16 h2 = __float2bfloat16(s.z);
    __nv_bfloat16 h3 = __float2bfloat16(s.w);
    uint16_t u0 = *reinterpret_cast<uint16_t*>(&h0);
    uint16_t u1 = *reinterpret_cast<uint16_t*>(&h1);
    uint16_t u2 = *reinterpret_cast<uint16_t*>(&h2);
    uint16_t u3 = *reinterpret_cast<uint16_t*>(&h3);
    uint2 hv, lv;
    hv.x = ((uint32_t)u1 << 16) | u0;
    hv.y = ((uint32_t)u3 << 16) | u2;
    lv.x = pack_bf16(s.x - __bfloat162float(h0), s.y - __bfloat162float(h1));
    lv.y = pack_bf16(s.z - __bfloat162float(h2), s.w - __bfloat162float(h3));
    *(uint2*)(rb + t * 8) = hv;
    *(uint2*)(rb + 512 + t * 8) = lv;

    float ss = s.x * s.x + s.y * s.y + s.z * s.z + s.w * s.w;
    #pragma unroll
    for (int o = 16; o > 0; o >>= 1) ss += __shfl_xor_sync(0xffffffffu, ss, o);
    __shared__ float part[2];
    if ((t & 31) == 0) part[t >> 5] = ss;
    __syncthreads();
    if (t == 0) *sqdst = part[0] + part[1];
}

// ---------------------------------------------------------------------------
// Kernel 2: mma.sync bf16 mining GEMM (3-segment hi/lo, exact to ~2^-17).
// CTA = 128 anchors x class, 256 threads (8 warps 2x4). A ext tile (128KB)
// resident in SMEM. B streamed as 32KB chunks, 3-stage ring, ONE
// __syncthreads per chunk. 4 chunks per j-tile:
//   c0: B hi k0..127   -> A hi0 + A lo0   (2 segments, B frags reused)
//   c1: B hi k128..255 -> A hi1 + A lo1
//   c2: B lo k0..127   -> A hi0
//   c3: B lo k128..255 -> A hi1
// Epilogue at c3: dis = clip(xx + yy - 2 acc, 0); running argmax/argmin.
// ---------------------------------------------------------------------------
#define OFF_A   0u
#define OFF_B   131072u
#define OFF_YY0 229376u
#define OFF_YY1 229888u
#define SMEM_SZ 230400
#define NCHUNK  128

__device__ __forceinline__ void prefetch_chunk(int g, int tid, uint32_t sbase,
                                               const unsigned char* posb,
                                               const unsigned char* negb,
                                               const float* psq, const float* nsq) {
    int jt = g >> 2, c = g & 3;
    const unsigned char* rb = (jt < 16)
        ? (posb + (size_t)(jt * 128) * ROW_BYTES)
        : (negb + (size_t)((jt - 16) * 128) * ROW_BYTES);
    rb += c * 256;
    uint32_t dst = sbase + OFF_B + (uint32_t)(((uint32_t)g) % 3u) * 32768u;
    #pragma unroll
    for (int it = 0; it < 8; it++) {
        int i = tid + it * 256;
        int r = i >> 4, cl = i & 15;
        uint32_t cls16 = (uint32_t)((cl & 8) | ((cl ^ r) & 7));
        CP_ASYNC16(dst + (uint32_t)r * 256u + cls16 * 16u,
                   rb + (size_t)r * ROW_BYTES + cl * 16);
    }
    if (c == 0 && tid < 32) {
        const float* ys = (jt < 16) ? (psq + jt * 128) : (nsq + (jt - 16) * 128);
        CP_ASYNC16(sbase + ((jt & 1) ? OFF_YY1 : OFF_YY0) + (uint32_t)tid * 16u,
                   ys + tid * 4);
    }
}

__global__ void __launch_bounds__(256, 1) mine_kernel() {
    extern __shared__ __align__(16) unsigned char smem[];
    const int cls  = blockIdx.y;
    const int row0 = blockIdx.x * 128;
    const int tid  = threadIdx.x;
    const int lane = tid & 31;
    const int wid  = tid >> 5;
    const int wm   = wid >> 2;        // 0..1
    const int wn   = wid & 3;         // 0..3
    const uint32_t sbase = smem_u32(smem);

    const unsigned char* posb = g_posb + (size_t)cls * PP * ROW_BYTES;
    const unsigned char* negb = g_negb + (size_t)cls * QQ * ROW_BYTES;
    const float* psq = g_pos_sq + cls * PP;
    const float* nsq = g_neg_sq + cls * QQ;

    // ---- resident A ext tile (128 rows x 1KB), XOR-swizzled ----
    {
        const unsigned char* asrc = posb + (size_t)row0 * ROW_BYTES;
        #pragma unroll
        for (int it = 0; it < 32; it++) {
            int i = tid + it * 256;          // 0..8191
            int r = i >> 6, c16 = i & 63;
            uint32_t c16s = (uint32_t)((c16 & ~7) | ((c16 ^ r) & 7));
            CP_ASYNC16(sbase + OFF_A + (uint32_t)r * 1024u + c16s * 16u,
                       asrc + (size_t)r * ROW_BYTES + c16 * 16);
        }
    }
    CP_COMMIT();
    prefetch_chunk(0, tid, sbase, posb, negb, psq, nsq);
    CP_COMMIT();
    prefetch_chunk(1, tid, sbase, posb, negb, psq, nsq);
    CP_COMMIT();

    // ---- per-lane constants ----
    const int rrA = wm * 64 + (lane & 15);       // A ldmatrix row (within 128)
    const int khA = (lane >> 4) & 1;
    const int nB  = wn * 32 + (lane & 7);        // B ldmatrix row base
    const int khB = (lane >> 3) & 1;
    uint32_t aRow[4];
    #pragma unroll
    for (int mt = 0; mt < 4; mt++)
        aRow[mt] = sbase + OFF_A + (uint32_t)(rrA + mt * 16) * 1024u;

    float xxv[8];
    #pragma unroll
    for (int mt = 0; mt < 4; mt++) {
        int r0 = wm * 64 + mt * 16 + (lane >> 2);
        xxv[mt * 2]     = psq[row0 + r0];
        xxv[mt * 2 + 1] = psq[row0 + r0 + 8];
    }

    float acc[64];
    #pragma unroll
    for (int i = 0; i < 64; i++) acc[i] = 0.0f;

    float bpv[8], bnv[8];
    int   bpj[8], bnj[8];
    #pragma unroll
    for (int i = 0; i < 8; i++) {
        bpv[i] = -1e30f; bpj[i] = 0;
        bnv[i] =  1e30f; bnj[i] = 0;
    }

    for (int g = 0; g < NCHUNK; g++) {
        CP_WAIT1();                    // chunk g (and A on g=0) resident
        __syncthreads();               // visible to all; prior compute done
        if (g + 2 < NCHUNK)
            prefetch_chunk(g + 2, tid, sbase, posb, negb, psq, nsq);
        CP_COMMIT();                   // commit every iter for group accounting

        const int jt = g >> 2, c = g & 3;
        const uint32_t sbB = sbase + OFF_B + (uint32_t)(((uint32_t)g) % 3u) * 32768u;
        uint32_t bRow[4];
        #pragma unroll
        for (int nt = 0; nt < 4; nt++)
            bRow[nt] = sbB + (uint32_t)(nB + nt * 8) * 256u;

        const int uhi = (c & 1) * 16;          // A hi segment (16B units)
        if (c < 2) {
            const int ulo = 32 + (c & 1) * 16; // A lo segment
            #pragma unroll
            for (int s = 0; s < 8; s++) {
                uint32_t b0[4], b1[4];
                #pragma unroll
                for (int nt = 0; nt < 4; nt++) {
                    int cl = s * 2 + khB;
                    uint32_t cls16 = (uint32_t)((cl & 8) | ((cl ^ nB) & 7));
                    LDSM_X2(b0[nt], b1[nt], bRow[nt] + cls16 * 16u);
                }
                {
                    uint32_t a0[4], a1[4], a2[4], a3[4];
                    #pragma unroll
                    for (int mt = 0; mt < 4; mt++) {
                        int u = uhi + s * 2 + khA;
                        uint32_t us = (uint32_t)((u & ~7) | ((u ^ rrA) & 7));
                        LDSM_X4(a0[mt], a1[mt], a2[mt], a3[mt], aRow[mt] + us * 16u);
                    }
                    #pragma unroll
                    for (int mt = 0; mt < 4; mt++)
                        #pragma unroll
                        for (int nt = 0; nt < 4; nt++) {
                            int ai = (mt * 4 + nt) * 4;
                            MMA16816(acc[ai], acc[ai + 1], acc[ai + 2], acc[ai + 3],
                                     a0[mt], a1[mt], a2[mt], a3[mt], b0[nt], b1[nt]);
                        }
                }
                {
                    uint32_t a0[4], a1[4], a2[4], a3[4];
                    #pragma unroll
                    for (int mt = 0; mt < 4; mt++) {
                        int u = ulo + s * 2 + khA;
                        uint32_t us = (uint32_t)((u & ~7) | ((u ^ rrA) & 7));
                        LDSM_X4(a0[mt], a1[mt], a2[mt], a3[mt], aRow[mt] + us * 16u);
                    }
                    #pragma unroll
                    for (int mt = 0; mt < 4; mt++)
                        #pragma unroll
                        for (int nt = 0; nt < 4; nt++) {
                            int ai = (mt * 4 + nt) * 4;
                            MMA16816(acc[ai], acc[ai + 1], acc[ai + 2], acc[ai + 3],
                                     a0[mt], a1[mt], a2[mt], a3[mt], b0[nt], b1[nt]);
                        }
                }
            }
        } else {
            #pragma unroll
            for (int s = 0; s < 8; s++) {
                uint32_t b0[4], b1[4];
                #pragma unroll
                for (int nt = 0; nt < 4; nt++) {
                    int cl = s * 2 + khB;
                    uint32_t cls16 = (uint32_t)((cl & 8) | ((cl ^ nB) & 7));
                    LDSM_X2(b0[nt], b1[nt], bRow[nt] + cls16 * 16u);
                }
                uint32_t a0[4], a1[4], a2[4], a3[4];
                #pragma unroll
                for (int mt = 0; mt < 4; mt++) {
                    int u = uhi + s * 2 + khA;
                    uint32_t us = (uint32_t)((u & ~7) | ((u ^ rrA) & 7));
                    LDSM_X4(a0[mt], a1[mt], a2[mt], a3[mt], aRow[mt] + us * 16u);
                }
                #pragma unroll
                for (int mt = 0; mt < 4; mt++)
                    #pragma unroll
                    for (int nt = 0; nt < 4; nt++) {
                        int ai = (mt * 4 + nt) * 4;
                        MMA16816(acc[ai], acc[ai + 1], acc[ai + 2], acc[ai + 3],
                                 a0[mt], a1[mt], a2[mt], a3[mt], b0[nt], b1[nt]);
                    }
            }
        }

        if (c == 3) {
            const float* yy = (const float*)(smem + ((jt & 1) ? OFF_YY1 : OFF_YY0));
            const bool isneg = jt >= 16;
            const int jbase = (isneg ? (jt - 16) : jt) * 128 + wn * 32;
            #pragma unroll
            for (int mt = 0; mt < 4; mt++) {
                #pragma unroll
                for (int nt = 0; nt < 4; nt++) {
                    int ai = (mt * 4 + nt) * 4;
                    int n = nt * 8 + ((lane & 3) << 1);
                    float y0 = yy[wn * 32 + n], y1 = yy[wn * 32 + n + 1];
                    float d00 = fmaxf(fmaf(-2.0f, acc[ai],     xxv[mt*2]   + y0), 0.0f);
                    float d01 = fmaxf(fmaf(-2.0f, acc[ai + 1], xxv[mt*2]   + y1), 0.0f);
                    float d10 = fmaxf(fmaf(-2.0f, acc[ai + 2], xxv[mt*2+1] + y0), 0.0f);
                    float d11 = fmaxf(fmaf(-2.0f, acc[ai + 3], xxv[mt*2+1] + y1), 0.0f);
                    int j0 = jbase + n, j1 = j0 + 1;
                    if (!isneg) {
                        if (d00 > bpv[mt*2])   { bpv[mt*2]   = d00; bpj[mt*2]   = j0; }
                        if (d01 > bpv[mt*2])   { bpv[mt*2]   = d01; bpj[mt*2]   = j1; }
                        if (d10 > bpv[mt*2+1]) { bpv[mt*2+1] = d10; bpj[mt*2+1] = j0; }
                        if (d11 > bpv[mt*2+1]) { bpv[mt*2+1] = d11; bpj[mt*2+1] = j1; }
                    } else {
                        if (d00 < bnv[mt*2])   { bnv[mt*2]   = d00; bnj[mt*2]   = j0; }
                        if (d01 < bnv[mt*2])   { bnv[mt*2]   = d01; bnj[mt*2]   = j1; }
                        if (d10 < bnv[mt*2+1]) { bnv[mt*2+1] = d10; bnj[mt*2+1] = j0; }
                        if (d11 < bnv[mt*2+1]) { bnv[mt*2+1] = d11; bnj[mt*2+1] = j1; }
                    }
                    acc[ai] = acc[ai + 1] = acc[ai + 2] = acc[ai + 3] = 0.0f;
                }
            }
        }
    }

    // ---- final cross-copy reduction (16 copies per row), index tie-break ----
    __syncthreads();
    float* sPV = (float*)(smem + OFF_B);
    int*   sPJ = (int*)(smem + OFF_B + 8192);
    float* sNV = (float*)(smem + OFF_B + 16384);
    int*   sNJ = (int*)(smem + OFF_B + 24576);
    int copy = wn * 4 + (lane & 3);
    #pragma unroll
    for (int mt = 0; mt < 4; mt++) {
        #pragma unroll
        for (int h = 0; h < 2; h++) {
            int r = wm * 64 + mt * 16 + (lane >> 2) + 8 * h;
            sPV[r * 16 + copy] = bpv[mt * 2 + h];
            sPJ[r * 16 + copy] = bpj[mt * 2 + h];
            sNV[r * 16 + copy] = bnv[mt * 2 + h];
            sNJ[r * 16 + copy] = bnj[mt * 2 + h];
        }
    }
    __syncthreads();
    if (tid < 128) {
        int r = tid;
        float bv = sPV[r * 16]; int bj = sPJ[r * 16];
        #pragma unroll
        for (int x = 1; x < 16; x++) {
            float v = sPV[r * 16 + x]; int j = sPJ[r * 16 + x];
            if (v > bv || (v == bv && j < bj)) { bv = v; bj = j; }
        }
        g_hp[cls * PP + row0 + r] = bj;
        bv = sNV[r * 16]; bj = sNJ[r * 16];
        #pragma unroll
        for (int x = 1; x < 16; x++) {
            float v = sNV[r * 16 + x]; int j = sNJ[r * 16 + x];
            if (v < bv || (v == bv && j < bj)) { bv = v; bj = j; }
        }
        g_hn[cls * PP + row0 + r] = bj;
    }
}

// ---------------------------------------------------------------------------
// Kernel 3: per-anchor pdist + hinge (fp32 exact). One warp per anchor.
// ---------------------------------------------------------------------------
__global__ void __launch_bounds__(256) loss_kernel() {
    int warp = threadIdx.x >> 5;
    int lane = threadIdx.x & 31;
    int a = blockIdx.x * 8 + warp;
    int cls = a / PP;

    const float* x  = g_pos + (size_t)a * CC;
    const float* yp = g_pos + ((size_t)cls * PP + g_hp[a]) * CC;
    const float* yn = g_neg + ((size_t)cls * QQ + g_hn[a]) * CC;

    float sp = 0.0f, sn = 0.0f;
    #pragma unroll
    for (int c4 = lane; c4 < CC / 4; c4 += 32) {
        float4 xv = ((const float4*)x)[c4];
        float4 pv = ((const float4*)yp)[c4];
        float4 nv = ((const float4*)yn)[c4];
        float d;
        d = xv.x - pv.x; sp = fmaf(d, d, sp);
        d = xv.y - pv.y; sp = fmaf(d, d, sp);
        d = xv.z - pv.z; sp = fmaf(d, d, sp);
        d = xv.w - pv.w; sp = fmaf(d, d, sp);
        d = xv.x - nv.x; sn = fmaf(d, d, sn);
        d = xv.y - nv.y; sn = fmaf(d, d, sn);
        d = xv.z - nv.z; sn = fmaf(d, d, sn);
        d = xv.w - nv.w; sn = fmaf(d, d, sn);
    }
    #pragma unroll
    for (int o = 16; o > 0; o >>= 1) {
        sp += __shfl_xor_sync(0xffffffffu, sp, o);
        sn += __shfl_xor_sync(0xffffffffu, sn, o);
    }
    __shared__ float sl[8];
    if (lane == 0) {
        float dp = sqrtf(fmaxf(sp, 0.0f) + EPSV);
        float dn = sqrtf(fmaxf(sn, 0.0f) + EPSV);
        sl[warp] = fmaxf(0.3f + dp - dn, 0.0f);
    }
    __syncthreads();
    if (threadIdx.x == 0) {
        float s = 0.0f;
        #pragma unroll
        for (int w = 0; w < 8; w++) s += sl[w];
        g_partial[blockIdx.x] = s * (1.0f / (float)PP);
    }
}

__global__ void __launch_bounds__(1024) finalsum_kernel(float* __restrict__ out) {
    __shared__ float s[1024];
    float v = 0.0f;
    for (int i = threadIdx.x; i < NCLS * PP / 8; i += 1024) v += g_partial[i];
    s[threadIdx.x] = v;
    __syncthreads();
    for (int st = 512; st > 0; st >>= 1) {
        if (threadIdx.x < st) s[threadIdx.x] += s[threadIdx.x + st];
        __syncthreads();
    }
    if (threadIdx.x == 0) out[0] = s[0];
}

extern "C" void kernel_launch(void* const* d_in, const int* in_sizes, int n_in,
                              void* d_out, int out_size) {
    const float* feat = (const float*)d_in[0];
    const int* pidx = (const int*)d_in[1];
    const int* nidx = (const int*)d_in[2];
    float* out = (float*)d_out;

    cudaFuncSetAttribute(mine_kernel, cudaFuncAttributeMaxDynamicSharedMemorySize, SMEM_SZ);

    gather_kernel<<<NCLS * (PP + QQ), 64>>>(feat, pidx, nidx);
    mine_kernel<<<dim3(PP / 128, NCLS), 256, SMEM_SZ>>>();
    loss_kernel<<<NCLS * PP / 8, 256>>>();
    finalsum_kernel<<<1, 1024>>>(out);
}

// round 15
// speedup vs baseline: 4.1965x; 1.2529x over previous
#include <cuda_runtime.h>
#include <cuda_bf16.h>
#include <math.h>
#include <stdint.h>

// ---------------- problem constants ----------------
#define NCLS 20
#define PP 2048
#define QQ 2048
#define CC 256
#define EPSV (0.0001f / 256.0f)
#define NP (NCLS * PP)

// ext row: [hi(256) | lo(256)] bf16 = 1024 bytes
#define ROW_BYTES 1024

// ---------------- device scratch (static; no runtime alloc) ----------------
__device__ float g_pos[(size_t)NCLS * PP * CC];
__device__ float g_neg[(size_t)NCLS * QQ * CC];
__device__ float g_pos_sq[NCLS * PP];
__device__ float g_neg_sq[NCLS * QQ];
__device__ __align__(16) unsigned char g_posb[(size_t)NCLS * PP * ROW_BYTES];
__device__ __align__(16) unsigned char g_negb[(size_t)NCLS * QQ * ROW_BYTES];
__device__ float g_qpv[4 * NP];           // per-quarter best pos value
__device__ int   g_qpj[4 * NP];
__device__ float g_qnv[4 * NP];           // per-quarter best neg value
__device__ int   g_qnj[4 * NP];
__device__ int   g_hp[NP];
__device__ int   g_hn[NP];
__device__ float g_partial[NP / 8];

// ---------------- helpers ----------------
__device__ __forceinline__ uint32_t smem_u32(const void* p) {
    uint32_t a;
    asm("{ .reg .u64 t; cvta.to.shared.u64 t, %1; cvt.u32.u64 %0, t; }" : "=r"(a) : "l"(p));
    return a;
}
#define CP_ASYNC16(saddr, gptr) \
    asm volatile("cp.async.cg.shared.global [%0], [%1], 16;" :: "r"(saddr), "l"(gptr))
#define CP_COMMIT() asm volatile("cp.async.commit_group;" ::: "memory")
#define CP_WAIT1()  asm volatile("cp.async.wait_group 1;" ::: "memory")
#define CP_WAIT0()  asm volatile("cp.async.wait_group 0;" ::: "memory")

#define LDSM_X4(r0, r1, r2, r3, a) \
    asm volatile("ldmatrix.sync.aligned.m8n8.x4.shared.b16 {%0,%1,%2,%3}, [%4];" \
                 : "=r"(r0), "=r"(r1), "=r"(r2), "=r"(r3) : "r"(a))
#define LDSM_X2(r0, r1, a) \
    asm volatile("ldmatrix.sync.aligned.m8n8.x2.shared.b16 {%0,%1}, [%2];" \
                 : "=r"(r0), "=r"(r1) : "r"(a))
#define MMA16816(c0, c1, c2, c3, a0, a1, a2, a3, b0, b1) \
    asm volatile("mma.sync.aligned.m16n8k16.row.col.f32.bf16.bf16.f32 " \
                 "{%0,%1,%2,%3}, {%4,%5,%6,%7}, {%8,%9}, {%0,%1,%2,%3};" \
                 : "+f"(c0), "+f"(c1), "+f"(c2), "+f"(c3) \
                 : "r"(a0), "r"(a1), "r"(a2), "r"(a3), "r"(b0), "r"(b1))

__device__ __forceinline__ uint32_t pack_bf16(float a, float b) {
    __nv_bfloat16 ba = __float2bfloat16(a);
    __nv_bfloat16 bb = __float2bfloat16(b);
    uint16_t ua = *reinterpret_cast<uint16_t*>(&ba);
    uint16_t ub = *reinterpret_cast<uint16_t*>(&bb);
    return ((uint32_t)ub << 16) | (uint32_t)ua;
}

// ---------------------------------------------------------------------------
// Kernel 1: gather + sigmoid -> fp32 row, squared norm, and hi|lo bf16 ext row
// ---------------------------------------------------------------------------
__global__ void __launch_bounds__(64) gather_kernel(const float* __restrict__ feat,
                                                    const int* __restrict__ pidx,
                                                    const int* __restrict__ nidx) {
    int row = blockIdx.x;
    int t = threadIdx.x;
    int src;
    float* dst;
    float* sqdst;
    unsigned char* rb;
    if (row < NP) {
        src = pidx[row];
        dst = g_pos + (size_t)row * CC;
        sqdst = g_pos_sq + row;
        rb = g_posb + (size_t)row * ROW_BYTES;
    } else {
        int r = row - NP;
        src = nidx[r];
        dst = g_neg + (size_t)r * CC;
        sqdst = g_neg_sq + r;
        rb = g_negb + (size_t)r * ROW_BYTES;
    }
    float4 v = *(const float4*)(feat + (size_t)src * CC + t * 4);
    float4 s;
    s.x = 1.0f / (1.0f + expf(-v.x));
    s.y = 1.0f / (1.0f + expf(-v.y));
    s.z = 1.0f / (1.0f + expf(-v.z));
    s.w = 1.0f / (1.0f + expf(-v.w));
    *(float4*)(dst + t * 4) = s;

    __nv_bfloat16 h0 = __float2bfloat16(s.x);
    __nv_bfloat16 h1 = __float2bfloat16(s.y);
    __nv_bfloat16 h2 = __float2bfloat16(s.z);
    __nv_bfloat16 h3 = __float2bfloat16(s.w);
    uint16_t u0 = *reinterpret_cast<uint16_t*>(&h0);
    uint16_t u1 = *reinterpret_cast<uint16_t*>(&h1);
    uint16_t u2 = *reinterpret_cast<uint16_t*>(&h2);
    uint16_t u3 = *reinterpret_cast<uint16_t*>(&h3);
    uint2 hv, lv;
    hv.x = ((uint32_t)u1 << 16) | u0;
    hv.y = ((uint32_t)u3 << 16) | u2;
    lv.x = pack_bf16(s.x - __bfloat162float(h0), s.y - __bfloat162float(h1));
    lv.y = pack_bf16(s.z - __bfloat162float(h2), s.w - __bfloat162float(h3));
    *(uint2*)(rb + t * 8) = hv;
    *(uint2*)(rb + 512 + t * 8) = lv;

    float ss = s.x * s.x + s.y * s.y + s.z * s.z + s.w * s.w;
    #pragma unroll
    for (int o = 16; o > 0; o >>= 1) ss += __shfl_xor_sync(0xffffffffu, ss, o);
    __shared__ float part[2];
    if ((t & 31) == 0) part[t >> 5] = ss;
    __syncthreads();
    if (t == 0) *sqdst = part[0] + part[1];
}

// ---------------------------------------------------------------------------
// Kernel 2: mma.sync bf16 mining GEMM, j-split into 4 quarters.
// CTA = (128 anchors, class, quarter q). Quarter q handles pos j-tiles
// [4q,4q+4) and neg j-tiles [4q,4q+4): 8 local tiles x 4 chunks = 32 chunks.
// Compute core identical to the passing R12 kernel (3-segment hi/lo bf16).
// ---------------------------------------------------------------------------
#define OFF_A   0u
#define OFF_B   131072u
#define OFF_YY0 229376u
#define OFF_YY1 229888u
#define SMEM_SZ 230400
#define NCHUNK  32

__device__ __forceinline__ void prefetch_chunk(int g, int q, int tid, uint32_t sbase,
                                               const unsigned char* posb,
                                               const unsigned char* negb,
                                               const float* psq, const float* nsq) {
    int lt = g >> 2, c = g & 3;          // lt in 0..7
    int gjt = q * 4 + (lt & 3);          // global j-tile 0..15
    bool isp = lt < 4;
    const unsigned char* rb = (isp ? posb : negb) + (size_t)(gjt * 128) * ROW_BYTES;
    rb += c * 256;
    uint32_t dst = sbase + OFF_B + (uint32_t)(((uint32_t)g) % 3u) * 32768u;
    #pragma unroll
    for (int it = 0; it < 8; it++) {
        int i = tid + it * 256;
        int r = i >> 4, cl = i & 15;
        uint32_t cls16 = (uint32_t)((cl & 8) | ((cl ^ r) & 7));
        CP_ASYNC16(dst + (uint32_t)r * 256u + cls16 * 16u,
                   rb + (size_t)r * ROW_BYTES + cl * 16);
    }
    if (c == 0 && tid < 32) {
        const float* ys = (isp ? psq : nsq) + gjt * 128;
        CP_ASYNC16(sbase + ((lt & 1) ? OFF_YY1 : OFF_YY0) + (uint32_t)tid * 16u,
                   ys + tid * 4);
    }
}

__global__ void __launch_bounds__(256, 1) mine_kernel() {
    extern __shared__ __align__(16) unsigned char smem[];
    const int cls  = blockIdx.y;
    const int row0 = blockIdx.x * 128;
    const int q    = blockIdx.z;
    const int tid  = threadIdx.x;
    const int lane = tid & 31;
    const int wid  = tid >> 5;
    const int wm   = wid >> 2;        // 0..1
    const int wn   = wid & 3;         // 0..3
    const uint32_t sbase = smem_u32(smem);

    const unsigned char* posb = g_posb + (size_t)cls * PP * ROW_BYTES;
    const unsigned char* negb = g_negb + (size_t)cls * QQ * ROW_BYTES;
    const float* psq = g_pos_sq + cls * PP;
    const float* nsq = g_neg_sq + cls * QQ;

    // ---- resident A ext tile (128 rows x 1KB), XOR-swizzled ----
    {
        const unsigned char* asrc = posb + (size_t)row0 * ROW_BYTES;
        #pragma unroll
        for (int it = 0; it < 32; it++) {
            int i = tid + it * 256;          // 0..8191
            int r = i >> 6, c16 = i & 63;
            uint32_t c16s = (uint32_t)((c16 & ~7) | ((c16 ^ r) & 7));
            CP_ASYNC16(sbase + OFF_A + (uint32_t)r * 1024u + c16s * 16u,
                       asrc + (size_t)r * ROW_BYTES + c16 * 16);
        }
    }
    CP_COMMIT();
    prefetch_chunk(0, q, tid, sbase, posb, negb, psq, nsq);
    CP_COMMIT();
    prefetch_chunk(1, q, tid, sbase, posb, negb, psq, nsq);
    CP_COMMIT();

    // ---- per-lane constants ----
    const int rrA = wm * 64 + (lane & 15);
    const int khA = (lane >> 4) & 1;
    const int nB  = wn * 32 + (lane & 7);
    const int khB = (lane >> 3) & 1;
    uint32_t aRow[4];
    #pragma unroll
    for (int mt = 0; mt < 4; mt++)
        aRow[mt] = sbase + OFF_A + (uint32_t)(rrA + mt * 16) * 1024u;

    float xxv[8];
    #pragma unroll
    for (int mt = 0; mt < 4; mt++) {
        int r0 = wm * 64 + mt * 16 + (lane >> 2);
        xxv[mt * 2]     = psq[row0 + r0];
        xxv[mt * 2 + 1] = psq[row0 + r0 + 8];
    }

    float acc[64];
    #pragma unroll
    for (int i = 0; i < 64; i++) acc[i] = 0.0f;

    float bpv[8], bnv[8];
    int   bpj[8], bnj[8];
    #pragma unroll
    for (int i = 0; i < 8; i++) {
        bpv[i] = -1e30f; bpj[i] = 0;
        bnv[i] =  1e30f; bnj[i] = 0;
    }

    for (int g = 0; g < NCHUNK; g++) {
        CP_WAIT1();
        __syncthreads();
        if (g + 2 < NCHUNK)
            prefetch_chunk(g + 2, q, tid, sbase, posb, negb, psq, nsq);
        CP_COMMIT();

        const int lt = g >> 2, c = g & 3;
        const uint32_t sbB = sbase + OFF_B + (uint32_t)(((uint32_t)g) % 3u) * 32768u;
        uint32_t bRow[4];
        #pragma unroll
        for (int nt = 0; nt < 4; nt++)
            bRow[nt] = sbB + (uint32_t)(nB + nt * 8) * 256u;

        const int uhi = (c & 1) * 16;
        if (c < 2) {
            const int ulo = 32 + (c & 1) * 16;
            #pragma unroll
            for (int s = 0; s < 8; s++) {
                uint32_t b0[4], b1[4];
                #pragma unroll
                for (int nt = 0; nt < 4; nt++) {
                    int cl = s * 2 + khB;
                    uint32_t cls16 = (uint32_t)((cl & 8) | ((cl ^ nB) & 7));
                    LDSM_X2(b0[nt], b1[nt], bRow[nt] + cls16 * 16u);
                }
                {
                    uint32_t a0[4], a1[4], a2[4], a3[4];
                    #pragma unroll
                    for (int mt = 0; mt < 4; mt++) {
                        int u = uhi + s * 2 + khA;
                        uint32_t us = (uint32_t)((u & ~7) | ((u ^ rrA) & 7));
                        LDSM_X4(a0[mt], a1[mt], a2[mt], a3[mt], aRow[mt] + us * 16u);
                    }
                    #pragma unroll
                    for (int mt = 0; mt < 4; mt++)
                        #pragma unroll
                        for (int nt = 0; nt < 4; nt++) {
                            int ai = (mt * 4 + nt) * 4;
                            MMA16816(acc[ai], acc[ai + 1], acc[ai + 2], acc[ai + 3],
                                     a0[mt], a1[mt], a2[mt], a3[mt], b0[nt], b1[nt]);
                        }
                }
                {
                    uint32_t a0[4], a1[4], a2[4], a3[4];
                    #pragma unroll
                    for (int mt = 0; mt < 4; mt++) {
                        int u = ulo + s * 2 + khA;
                        uint32_t us = (uint32_t)((u & ~7) | ((u ^ rrA) & 7));
                        LDSM_X4(a0[mt], a1[mt], a2[mt], a3[mt], aRow[mt] + us * 16u);
                    }
                    #pragma unroll
                    for (int mt = 0; mt < 4; mt++)
                        #pragma unroll
                        for (int nt = 0; nt < 4; nt++) {
                            int ai = (mt * 4 + nt) * 4;
                            MMA16816(acc[ai], acc[ai + 1], acc[ai + 2], acc[ai + 3],
                                     a0[mt], a1[mt], a2[mt], a3[mt], b0[nt], b1[nt]);
                        }
                }
            }
        } else {
            #pragma unroll
            for (int s = 0; s < 8; s++) {
                uint32_t b0[4], b1[4];
                #pragma unroll
                for (int nt = 0; nt < 4; nt++) {
                    int cl = s * 2 + khB;
                    uint32_t cls16 = (uint32_t)((cl & 8) | ((cl ^ nB) & 7));
                    LDSM_X2(b0[nt], b1[nt], bRow[nt] + cls16 * 16u);
                }
                uint32_t a0[4], a1[4], a2[4], a3[4];
                #pragma unroll
                for (int mt = 0; mt < 4; mt++) {
                    int u = uhi + s * 2 + khA;
                    uint32_t us = (uint32_t)((u & ~7) | ((u ^ rrA) & 7));
                    LDSM_X4(a0[mt], a1[mt], a2[mt], a3[mt], aRow[mt] + us * 16u);
                }
                #pragma unroll
                for (int mt = 0; mt < 4; mt++)
                    #pragma unroll
                    for (int nt = 0; nt < 4; nt++) {
                        int ai = (mt * 4 + nt) * 4;
                        MMA16816(acc[ai], acc[ai + 1], acc[ai + 2], acc[ai + 3],
                                 a0[mt], a1[mt], a2[mt], a3[mt], b0[nt], b1[nt]);
                    }
            }
        }

        if (c == 3) {
            const float* yy = (const float*)(smem + ((lt & 1) ? OFF_YY1 : OFF_YY0));
            const bool isneg = lt >= 4;
            const int gjt = q * 4 + (lt & 3);
            const int jbase = gjt * 128 + wn * 32;
            #pragma unroll
            for (int mt = 0; mt < 4; mt++) {
                #pragma unroll
                for (int nt = 0; nt < 4; nt++) {
                    int ai = (mt * 4 + nt) * 4;
                    int n = nt * 8 + ((lane & 3) << 1);
                    float y0 = yy[wn * 32 + n], y1 = yy[wn * 32 + n + 1];
                    float d00 = fmaxf(fmaf(-2.0f, acc[ai],     xxv[mt*2]   + y0), 0.0f);
                    float d01 = fmaxf(fmaf(-2.0f, acc[ai + 1], xxv[mt*2]   + y1), 0.0f);
                    float d10 = fmaxf(fmaf(-2.0f, acc[ai + 2], xxv[mt*2+1] + y0), 0.0f);
                    float d11 = fmaxf(fmaf(-2.0f, acc[ai + 3], xxv[mt*2+1] + y1), 0.0f);
                    int j0 = jbase + n, j1 = j0 + 1;
                    if (!isneg) {
                        if (d00 > bpv[mt*2])   { bpv[mt*2]   = d00; bpj[mt*2]   = j0; }
                        if (d01 > bpv[mt*2])   { bpv[mt*2]   = d01; bpj[mt*2]   = j1; }
                        if (d10 > bpv[mt*2+1]) { bpv[mt*2+1] = d10; bpj[mt*2+1] = j0; }
                        if (d11 > bpv[mt*2+1]) { bpv[mt*2+1] = d11; bpj[mt*2+1] = j1; }
                    } else {
                        if (d00 < bnv[mt*2])   { bnv[mt*2]   = d00; bnj[mt*2]   = j0; }
                        if (d01 < bnv[mt*2])   { bnv[mt*2]   = d01; bnj[mt*2]   = j1; }
                        if (d10 < bnv[mt*2+1]) { bnv[mt*2+1] = d10; bnj[mt*2+1] = j0; }
                        if (d11 < bnv[mt*2+1]) { bnv[mt*2+1] = d11; bnj[mt*2+1] = j1; }
                    }
                    acc[ai] = acc[ai + 1] = acc[ai + 2] = acc[ai + 3] = 0.0f;
                }
            }
        }
    }

    // ---- cross-copy reduction (16 copies per row), index tie-break ----
    __syncthreads();
    float* sPV = (float*)(smem + OFF_B);
    int*   sPJ = (int*)(smem + OFF_B + 8192);
    float* sNV = (float*)(smem + OFF_B + 16384);
    int*   sNJ = (int*)(smem + OFF_B + 24576);
    int copy = wn * 4 + (lane & 3);
    #pragma unroll
    for (int mt = 0; mt < 4; mt++) {
        #pragma unroll
        for (int h = 0; h < 2; h++) {
            int r = wm * 64 + mt * 16 + (lane >> 2) + 8 * h;
            sPV[r * 16 + copy] = bpv[mt * 2 + h];
            sPJ[r * 16 + copy] = bpj[mt * 2 + h];
            sNV[r * 16 + copy] = bnv[mt * 2 + h];
            sNJ[r * 16 + copy] = bnj[mt * 2 + h];
        }
    }
    __syncthreads();
    if (tid < 128) {
        int r = tid;
        int outi = q * NP + cls * PP + row0 + r;
        float bv = sPV[r * 16]; int bj = sPJ[r * 16];
        #pragma unroll
        for (int x = 1; x < 16; x++) {
            float v = sPV[r * 16 + x]; int j = sPJ[r * 16 + x];
            if (v > bv || (v == bv && j < bj)) { bv = v; bj = j; }
        }
        g_qpv[outi] = bv; g_qpj[outi] = bj;
        bv = sNV[r * 16]; bj = sNJ[r * 16];
        #pragma unroll
        for (int x = 1; x < 16; x++) {
            float v = sNV[r * 16 + x]; int j = sNJ[r * 16 + x];
            if (v < bv || (v == bv && j < bj)) { bv = v; bj = j; }
        }
        g_qnv[outi] = bv; g_qnj[outi] = bj;
    }
}

// ---------------------------------------------------------------------------
// Kernel 2b: merge 4 quarters per anchor (ascending q = ascending j ranges).
// ---------------------------------------------------------------------------
__global__ void __launch_bounds__(256) merge_kernel() {
    int a = blockIdx.x * 256 + threadIdx.x;
    if (a >= NP) return;
    float bv = g_qpv[a]; int bj = g_qpj[a];
    #pragma unroll
    for (int qq = 1; qq < 4; qq++) {
        float v = g_qpv[qq * NP + a]; int j = g_qpj[qq * NP + a];
        if (v > bv || (v == bv && j < bj)) { bv = v; bj = j; }
    }
    g_hp[a] = bj;
    bv = g_qnv[a]; bj = g_qnj[a];
    #pragma unroll
    for (int qq = 1; qq < 4; qq++) {
        float v = g_qnv[qq * NP + a]; int j = g_qnj[qq * NP + a];
        if (v < bv || (v == bv && j < bj)) { bv = v; bj = j; }
    }
    g_hn[a] = bj;
}

// ---------------------------------------------------------------------------
// Kernel 3: per-anchor pdist + hinge (fp32 exact). One warp per anchor.
// ---------------------------------------------------------------------------
__global__ void __launch_bounds__(256) loss_kernel() {
    int warp = threadIdx.x >> 5;
    int lane = threadIdx.x & 31;
    int a = blockIdx.x * 8 + warp;
    int cls = a / PP;

    const float* x  = g_pos + (size_t)a * CC;
    const float* yp = g_pos + ((size_t)cls * PP + g_hp[a]) * CC;
    const float* yn = g_neg + ((size_t)cls * QQ + g_hn[a]) * CC;

    float sp = 0.0f, sn = 0.0f;
    #pragma unroll
    for (int c4 = lane; c4 < CC / 4; c4 += 32) {
        float4 xv = ((const float4*)x)[c4];
        float4 pv = ((const float4*)yp)[c4];
        float4 nv = ((const float4*)yn)[c4];
        float d;
        d = xv.x - pv.x; sp = fmaf(d, d, sp);
        d = xv.y - pv.y; sp = fmaf(d, d, sp);
        d = xv.z - pv.z; sp = fmaf(d, d, sp);
        d = xv.w - pv.w; sp = fmaf(d, d, sp);
        d = xv.x - nv.x; sn = fmaf(d, d, sn);
        d = xv.y - nv.y; sn = fmaf(d, d, sn);
        d = xv.z - nv.z; sn = fmaf(d, d, sn);
        d = xv.w - nv.w; sn = fmaf(d, d, sn);
    }
    #pragma unroll
    for (int o = 16; o > 0; o >>= 1) {
        sp += __shfl_xor_sync(0xffffffffu, sp, o);
        sn += __shfl_xor_sync(0xffffffffu, sn, o);
    }
    __shared__ float sl[8];
    if (lane == 0) {
        float dp = sqrtf(fmaxf(sp, 0.0f) + EPSV);
        float dn = sqrtf(fmaxf(sn, 0.0f) + EPSV);
        sl[warp] = fmaxf(0.3f + dp - dn, 0.0f);
    }
    __syncthreads();
    if (threadIdx.x == 0) {
        float s = 0.0f;
        #pragma unroll
        for (int w = 0; w < 8; w++) s += sl[w];
        g_partial[blockIdx.x] = s * (1.0f / (float)PP);
    }
}

__global__ void __launch_bounds__(1024) finalsum_kernel(float* __restrict__ out) {
    __shared__ float s[1024];
    float v = 0.0f;
    for (int i = threadIdx.x; i < NP / 8; i += 1024) v += g_partial[i];
    s[threadIdx.x] = v;
    __syncthreads();
    for (int st = 512; st > 0; st >>= 1) {
        if (threadIdx.x < st) s[threadIdx.x] += s[threadIdx.x + st];
        __syncthreads();
    }
    if (threadIdx.x == 0) out[0] = s[0];
}

extern "C" void kernel_launch(void* const* d_in, const int* in_sizes, int n_in,
                              void* d_out, int out_size) {
    const float* feat = (const float*)d_in[0];
    const int* pidx = (const int*)d_in[1];
    const int* nidx = (const int*)d_in[2];
    float* out = (float*)d_out;

    cudaFuncSetAttribute(mine_kernel, cudaFuncAttributeMaxDynamicSharedMemorySize, SMEM_SZ);

    gather_kernel<<<NCLS * (PP + QQ), 64>>>(feat, pidx, nidx);
    mine_kernel<<<dim3(PP / 128, NCLS, 4), 256, SMEM_SZ>>>();
    merge_kernel<<<(NP + 255) / 256, 256>>>();
    loss_kernel<<<NP / 8, 256>>>();
    finalsum_kernel<<<1, 1024>>>(out);
}